// round 15
// baseline (speedup 1.0000x reference)
#include <cuda_runtime.h>
#include <cuda_fp16.h>
#include <cstdint>

#define BB 2
#define SS 2048
#define DD 1024
#define HH 16
#define HD 64
#define GM (BB*SS)   // 4096
#define GN DD
#define GK DD

// ---------------------------------------------------------------------------
// Device-global scratch (fp16)
// ---------------------------------------------------------------------------
__device__ __half g_xhi[GM*DD];
__device__ __half g_wThi[4*DD*DD];      // W^T [N,K]
__device__ __half g_qhi[GM*DD];          // [B,H,S,HD], pre-scaled log2e/8
__device__ __half g_khi[GM*DD];
__device__ __half g_vhi[GM*DD];
__device__ __half g_ohi[GM*DD];          // [B*S, D] attn out

// ---------------------------------------------------------------------------
// Helpers
// ---------------------------------------------------------------------------
__device__ __forceinline__ uint32_t smem_u32(const void* p) {
    uint32_t a;
    asm("{ .reg .u64 t; cvta.to.shared.u64 t, %1; cvt.u32.u64 %0, t; }"
        : "=r"(a) : "l"(p));
    return a;
}

__device__ __forceinline__ uint32_t swz(uint32_t row, uint32_t cc) {
    return row * 128u + ((cc ^ (row & 7u)) << 4);
}

__device__ __forceinline__ void cp_async16(uint32_t s, const void* g) {
    asm volatile("cp.async.cg.shared.global [%0], [%1], 16;" :: "r"(s), "l"(g));
}
__device__ __forceinline__ void cp_async4(uint32_t s, const void* g) {
    asm volatile("cp.async.ca.shared.global [%0], [%1], 4;" :: "r"(s), "l"(g));
}
#define CP_COMMIT()  asm volatile("cp.async.commit_group;")
#define CP_WAIT2()   asm volatile("cp.async.wait_group 2;")
#define CP_WAIT1()   asm volatile("cp.async.wait_group 1;")
#define CP_WAIT0()   asm volatile("cp.async.wait_group 0;")

__device__ __forceinline__ void ldsm_x4(uint32_t* r, uint32_t a) {
    asm volatile("ldmatrix.sync.aligned.m8n8.x4.shared.b16 {%0,%1,%2,%3}, [%4];"
        : "=r"(r[0]), "=r"(r[1]), "=r"(r[2]), "=r"(r[3]) : "r"(a));
}
__device__ __forceinline__ void ldsm_x4_t(uint32_t* r, uint32_t a) {
    asm volatile("ldmatrix.sync.aligned.m8n8.x4.trans.shared.b16 {%0,%1,%2,%3}, [%4];"
        : "=r"(r[0]), "=r"(r[1]), "=r"(r[2]), "=r"(r[3]) : "r"(a));
}

__device__ __forceinline__ void mma_f32(float* c, const uint32_t* a, const uint32_t* b) {
    asm volatile(
        "mma.sync.aligned.m16n8k16.row.col.f32.f16.f16.f32 "
        "{%0,%1,%2,%3}, {%4,%5,%6,%7}, {%8,%9}, {%0,%1,%2,%3};"
        : "+f"(c[0]), "+f"(c[1]), "+f"(c[2]), "+f"(c[3])
        : "r"(a[0]), "r"(a[1]), "r"(a[2]), "r"(a[3]), "r"(b[0]), "r"(b[1]));
}

__device__ __forceinline__ uint32_t hpack(float a, float b) {
    __half2 h = __floats2half2_rn(a, b);
    return *reinterpret_cast<uint32_t*>(&h);
}

// single MUFU.EX2
__device__ __forceinline__ float ex2(float x) {
    float r;
    asm("ex2.approx.f32 %0, %1;" : "=f"(r) : "f"(x));
    return r;
}

// ---------------------------------------------------------------------------
// Merged prep: z=0..3 transpose W[z] -> W^T fp16; z=4 convert x -> fp16.
// ---------------------------------------------------------------------------
__global__ __launch_bounds__(256)
void prep_all(const float* __restrict__ x,
              const float* __restrict__ W0, const float* __restrict__ W1,
              const float* __restrict__ W2, const float* __restrict__ W3,
              __half* __restrict__ xhi, __half* __restrict__ hiT)
{
    const int z = blockIdx.z;
    const int tid = threadIdx.y * 32 + threadIdx.x;
    if (z == 4) {
        const int bid = blockIdx.y * 32 + blockIdx.x;
        const float4* src = (const float4*)x + (size_t)bid * 1024;
        uint32_t* dst = (uint32_t*)xhi + (size_t)bid * 2048;
#pragma unroll
        for (int it = 0; it < 4; ++it) {
            const int i = it * 256 + tid;
            float4 v = src[i];
            dst[2*i]   = hpack(v.x, v.y);
            dst[2*i+1] = hpack(v.z, v.w);
        }
        return;
    }
    __shared__ float t[32][33];
    const float* W = (z == 0) ? W0 : (z == 1) ? W1 : (z == 2) ? W2 : W3;
    __half* ho = hiT + (size_t)z * DD * DD;
    const int tx = threadIdx.x, ty = threadIdx.y;
    const int n0 = blockIdx.x * 32, k0 = blockIdx.y * 32;
#pragma unroll
    for (int r = ty; r < 32; r += 8)
        t[r][tx] = W[(size_t)(k0 + r) * GN + n0 + tx];
    __syncthreads();
#pragma unroll
    for (int r = ty; r < 32; r += 8)
        ho[(size_t)(n0 + r) * GK + k0 + tx] = __float2half_rn(t[tx][r]);
}

// ---------------------------------------------------------------------------
// GEMM core, 1-pass fp16, 3-stage cp.async pipeline.
// CTA 128x64, K-chunks of 64, 8 warps as 4M x 2N with cached fragments.
// ---------------------------------------------------------------------------
#define G_AH 0
#define G_BH 16384
#define G_STAGE 24576
#define G_SMEM (3*G_STAGE)   // 72KB -> 2 CTAs/SM (144KB)

struct GemmCtx {
    uint32_t sb;
    int arow, acc0, brow, bcc0;
    const __half *gAh, *gBh;
};

__device__ __forceinline__ void gemm_issue(const GemmCtx& g, int stage) {
    const uint32_t buf = g.sb + (stage % 3) * G_STAGE;
    const int ko = stage * 64;
#pragma unroll
    for (int i = 0; i < 4; ++i)
        cp_async16(buf + G_AH + swz(g.arow, g.acc0 + i), g.gAh + ko + i * 8);
#pragma unroll
    for (int i = 0; i < 2; ++i)
        cp_async16(buf + G_BH + swz(g.brow, g.bcc0 + i), g.gBh + ko + i * 8);
    CP_COMMIT();
}

__device__ __forceinline__ void gemm_mainloop(const GemmCtx& g, int lane,
                                              int wm, int wn, float c[2][4][4]) {
    gemm_issue(g, 0);
    gemm_issue(g, 1);
    for (int s = 0; s < 16; ++s) {
        if (s + 2 < 16)      { gemm_issue(g, s + 2); CP_WAIT2(); }
        else if (s + 1 < 16) { CP_WAIT1(); }
        else                 { CP_WAIT0(); }
        __syncthreads();
        const uint32_t base = g.sb + (s % 3) * G_STAGE;
#pragma unroll
        for (int kt = 0; kt < 4; ++kt) {
            uint32_t a0[4], a1[4];
            const uint32_t ar = wm * 32 + (lane & 15);
            const uint32_t ac = kt * 2 + (lane >> 4);
            ldsm_x4(a0, base + G_AH + swz(ar, ac));
            ldsm_x4(a1, base + G_AH + swz(ar + 16, ac));
#pragma unroll
            for (int np = 0; np < 2; ++np) {
                uint32_t bh[4];
                const uint32_t br  = wn * 32 + (2 * np + (lane >> 4)) * 8 + (lane & 7);
                const uint32_t bcc = kt * 2 + ((lane >> 3) & 1);
                ldsm_x4(bh, base + G_BH + swz(br, bcc));
                mma_f32(c[0][2*np],   a0, bh); mma_f32(c[0][2*np+1], a0, bh + 2);
                mma_f32(c[1][2*np],   a1, bh); mma_f32(c[1][2*np+1], a1, bh + 2);
            }
        }
        __syncthreads();
    }
}

// Fused QKV projection (1-pass): grid (16, 32, 3)
// Q scale folds softmax 1/sqrt(HD) AND log2(e).
__global__ __launch_bounds__(256, 2)
void gemm_qkv(const __half* __restrict__ Ahi, const __half* __restrict__ Whi,
              const float* __restrict__ bq, const float* __restrict__ bk,
              const float* __restrict__ bv,
              __half* __restrict__ qhi, __half* __restrict__ khi,
              __half* __restrict__ vhi)
{
    extern __shared__ char smraw[];
    const int tid = threadIdx.x, lane = tid & 31, warp = tid >> 5;
    const int wm = warp >> 1, wn = warp & 1;
    const int m0 = blockIdx.y * 128, n0 = blockIdx.x * 64;
    const int z = blockIdx.z;

    const float* bias = (z == 0) ? bq : (z == 1) ? bk : bv;
    __half* Chi = (z == 0) ? qhi : (z == 1) ? khi : vhi;
    const float scale = (z == 0) ? (0.125f * 1.4426950408889634f) : 1.0f;
    const __half* Bhi = Whi + (size_t)z * DD * DD;

    GemmCtx g;
    g.sb = smem_u32(smraw);
    g.arow = tid >> 1;  g.acc0 = (tid & 1) * 4;
    g.brow = tid >> 2;  g.bcc0 = (tid & 3) * 2;
    g.gAh = Ahi + (size_t)(m0 + g.arow) * GK + g.acc0 * 8;
    g.gBh = Bhi + (size_t)(n0 + g.brow) * GK + g.bcc0 * 8;

    float c[2][4][4];
#pragma unroll
    for (int a = 0; a < 2; ++a)
#pragma unroll
        for (int b = 0; b < 4; ++b)
#pragma unroll
            for (int e = 0; e < 4; ++e) c[a][b][e] = 0.f;

    gemm_mainloop(g, lane, wm, wn, c);

#pragma unroll
    for (int mt = 0; mt < 2; ++mt) {
#pragma unroll
        for (int nt = 0; nt < 4; ++nt) {
            const int col = n0 + wn * 32 + nt * 8 + (lane & 3) * 2;
            const float2 bs = *(const float2*)(bias + col);
#pragma unroll
            for (int hf = 0; hf < 2; ++hf) {
                const int row = m0 + wm * 32 + mt * 16 + (lane >> 2) + hf * 8;
                const float v0 = (c[mt][nt][hf*2]     + bs.x) * scale;
                const float v1 = (c[mt][nt][hf*2 + 1] + bs.y) * scale;
                const int bb = row >> 11, sq = row & 2047;
                const int hh = col >> 6,  hd = col & 63;
                const size_t off = (((size_t)(bb * HH + hh)) * SS + sq) * HD + hd;
                *(uint32_t*)(Chi + off) = hpack(v0, v1);
            }
        }
    }
}

// Output projection (1-pass): fp32 C + bias
__global__ __launch_bounds__(256, 2)
void gemm_out(const __half* __restrict__ Ahi, const __half* __restrict__ Bhi,
              const float* __restrict__ bias, float* __restrict__ C)
{
    extern __shared__ char smraw[];
    const int tid = threadIdx.x, lane = tid & 31, warp = tid >> 5;
    const int wm = warp >> 1, wn = warp & 1;
    const int m0 = blockIdx.y * 128, n0 = blockIdx.x * 64;

    GemmCtx g;
    g.sb = smem_u32(smraw);
    g.arow = tid >> 1;  g.acc0 = (tid & 1) * 4;
    g.brow = tid >> 2;  g.bcc0 = (tid & 3) * 2;
    g.gAh = Ahi + (size_t)(m0 + g.arow) * GK + g.acc0 * 8;
    g.gBh = Bhi + (size_t)(n0 + g.brow) * GK + g.bcc0 * 8;

    float c[2][4][4];
#pragma unroll
    for (int a = 0; a < 2; ++a)
#pragma unroll
        for (int b = 0; b < 4; ++b)
#pragma unroll
            for (int e = 0; e < 4; ++e) c[a][b][e] = 0.f;

    gemm_mainloop(g, lane, wm, wn, c);

#pragma unroll
    for (int mt = 0; mt < 2; ++mt) {
#pragma unroll
        for (int nt = 0; nt < 4; ++nt) {
            const int col = n0 + wn * 32 + nt * 8 + (lane & 3) * 2;
            const float2 bs = *(const float2*)(bias + col);
#pragma unroll
            for (int hf = 0; hf < 2; ++hf) {
                const int row = m0 + wm * 32 + mt * 16 + (lane >> 2) + hf * 8;
                const float v0 = c[mt][nt][hf*2]     + bs.x;
                const float v1 = c[mt][nt][hf*2 + 1] + bs.y;
                *(float2*)(C + (size_t)row * GN + col) = make_float2(v0, v1);
            }
        }
    }
}

// ---------------------------------------------------------------------------
// Flash attention, fixed-shift softmax, 3-stage K/V pipeline.
// ---------------------------------------------------------------------------
#define F_QHI 0
#define F_ST0 16384
#define F_STSZ 16384
#define F_KHI 0
#define F_VHI 8192
#define F_EMI (F_ST0 + 3*F_STSZ)
#define F_CMI (F_EMI + 3*256)
#define F_SMEM (F_CMI + 512)

__global__ __launch_bounds__(256, 2)
void flash_mma(const int* __restrict__ cause, const int* __restrict__ effect,
               const float* __restrict__ strength)
{
    extern __shared__ char smraw[];
    const uint32_t sb = smem_u32(smraw);
    const int tid = threadIdx.x, lane = tid & 31, warp = tid >> 5;
    const int b = blockIdx.z, h = blockIdx.y, q0 = blockIdx.x * 128;
    const float fm1 = 1.0f - 0.5f * strength[0];

    const size_t headoff = ((size_t)(b * HH + h)) * SS;

    {   // prologue: Q-hi + cause mask (joins stage-0 commit group)
        const __half* qsrc = g_qhi + (headoff + q0) * HD;
        const int r = tid >> 1, c0 = (tid & 1) * 4;
#pragma unroll
        for (int i = 0; i < 4; ++i)
            cp_async16(sb + F_QHI + swz(r, c0 + i),
                       qsrc + (size_t)r * HD + (c0 + i) * 8);
        if (tid < 128) cp_async4(sb + F_CMI + tid * 4, cause + b * SS + q0 + tid);
    }

    auto issue = [&](int s) {
        const uint32_t st = sb + F_ST0 + (s % 3) * F_STSZ;
        const int kt0 = s * 64;
        const __half* srcs[2] = { g_khi + (headoff + kt0) * HD,
                                  g_vhi + (headoff + kt0) * HD };
        const int r = tid >> 2, cc0 = (tid & 3) * 2;
#pragma unroll
        for (int t = 0; t < 2; ++t)
#pragma unroll
            for (int i = 0; i < 2; ++i)
                cp_async16(st + t * 8192 + swz(r, cc0 + i),
                           srcs[t] + (size_t)r * HD + (cc0 + i) * 8);
        if (tid < 64) cp_async4(sb + F_EMI + (s % 3) * 256 + tid * 4,
                                effect + b * SS + kt0 + tid);
        CP_COMMIT();
    };

    issue(0);
    issue(1);

    float o[8][4];
#pragma unroll
    for (int i = 0; i < 8; ++i)
#pragma unroll
        for (int e = 0; e < 4; ++e) o[i][e] = 0.f;
    float lrow0 = 0.f, lrow1 = 0.f;
    uint32_t qh[4][4];
    int cm0 = 0, cm1 = 0;

    for (int s = 0; s < 32; ++s) {
        if (s + 2 < 32)      { issue(s + 2); CP_WAIT2(); }
        else if (s + 1 < 32) { CP_WAIT1(); }
        else                 { CP_WAIT0(); }
        __syncthreads();

        if (s == 0) {
            const uint32_t ar = warp * 16 + (lane & 15);
#pragma unroll
            for (int kt = 0; kt < 4; ++kt)
                ldsm_x4(qh[kt], sb + F_QHI + swz(ar, kt * 2 + (lane >> 4)));
            const int* cmi = (const int*)(smraw + F_CMI);
            cm0 = cmi[warp * 16 + (lane >> 2)];
            cm1 = cmi[warp * 16 + (lane >> 2) + 8];
        }

        const uint32_t st = sb + F_ST0 + (s % 3) * F_STSZ;

        // ---- S = Qh Kh  (log2 domain)
        float sc[8][4];
#pragma unroll
        for (int i = 0; i < 8; ++i)
            sc[i][0] = sc[i][1] = sc[i][2] = sc[i][3] = 0.f;
#pragma unroll
        for (int kt = 0; kt < 4; ++kt) {
#pragma unroll
            for (int np = 0; np < 4; ++np) {
                uint32_t kh[4];
                const uint32_t br  = (2 * np + (lane >> 4)) * 8 + (lane & 7);
                const uint32_t bcc = kt * 2 + ((lane >> 3) & 1);
                ldsm_x4(kh, st + F_KHI + swz(br, bcc));
                mma_f32(sc[2*np], qh[kt], kh); mma_f32(sc[2*np+1], qh[kt], kh + 2);
            }
        }

        // ---- mask + fixed-shift softmax: P = ex2(S*mask)
        const int* emi = (const int*)(smraw + F_EMI + (s % 3) * 256);
        uint32_t pha[8], phb[8];
#pragma unroll
        for (int nt = 0; nt < 8; ++nt) {
            const int col = nt * 8 + (lane & 3) * 2;
            const int e0 = emi[col], e1 = emi[col + 1];
            const float p0 = ex2(sc[nt][0] * ((cm0 && e0) ? fm1 : 1.0f));
            const float p1 = ex2(sc[nt][1] * ((cm0 && e1) ? fm1 : 1.0f));
            const float p2 = ex2(sc[nt][2] * ((cm1 && e0) ? fm1 : 1.0f));
            const float p3 = ex2(sc[nt][3] * ((cm1 && e1) ? fm1 : 1.0f));
            lrow0 += p0 + p1;
            lrow1 += p2 + p3;
            pha[nt] = hpack(p0, p1);
            phb[nt] = hpack(p2, p3);
        }

        // ---- O += Ph Vh
#pragma unroll
        for (int kt = 0; kt < 4; ++kt) {
            uint32_t ph[4] = { pha[2*kt], phb[2*kt], pha[2*kt+1], phb[2*kt+1] };
#pragma unroll
            for (int np = 0; np < 4; ++np) {
                uint32_t vh[4];
                const uint32_t vr  = kt * 16 + (((lane >> 3) & 1) << 3) + (lane & 7);
                const uint32_t vcc = 2 * np + (lane >> 4);
                ldsm_x4_t(vh, st + F_VHI + swz(vr, vcc));
                mma_f32(o[2*np], ph, vh); mma_f32(o[2*np+1], ph, vh + 2);
            }
        }
        __syncthreads();
    }

    // ---- epilogue: single cross-lane row-sum reduce, normalize, store
    lrow0 += __shfl_xor_sync(0xffffffffu, lrow0, 1);
    lrow0 += __shfl_xor_sync(0xffffffffu, lrow0, 2);
    lrow1 += __shfl_xor_sync(0xffffffffu, lrow1, 1);
    lrow1 += __shfl_xor_sync(0xffffffffu, lrow1, 2);
    const float inv0 = 1.0f / lrow0, inv1 = 1.0f / lrow1;
    const int row0 = b * SS + q0 + warp * 16 + (lane >> 2);
#pragma unroll
    for (int nt = 0; nt < 8; ++nt) {
        const int col = h * 64 + nt * 8 + (lane & 3) * 2;
        const float v0 = o[nt][0] * inv0, v1 = o[nt][1] * inv0;
        const float v2 = o[nt][2] * inv1, v3 = o[nt][3] * inv1;
        *(uint32_t*)(g_ohi + (size_t)row0 * DD + col)       = hpack(v0, v1);
        *(uint32_t*)(g_ohi + (size_t)(row0 + 8) * DD + col) = hpack(v2, v3);
    }
}

// ---------------------------------------------------------------------------
extern "C" void kernel_launch(void* const* d_in, const int* in_sizes, int n_in,
                              void* d_out, int out_size)
{
    const float* x        = (const float*)d_in[0];
    const int*   cause    = (const int*)d_in[1];
    const int*   effect   = (const int*)d_in[2];
    const float* strength = (const float*)d_in[3];
    const float* Wq = (const float*)d_in[4];
    const float* bq = (const float*)d_in[5];
    const float* Wk = (const float*)d_in[6];
    const float* bk = (const float*)d_in[7];
    const float* Wv = (const float*)d_in[8];
    const float* bv = (const float*)d_in[9];
    const float* Wo = (const float*)d_in[10];
    const float* bo = (const float*)d_in[11];
    float* out = (float*)d_out;

    void *pxhi, *pwhi, *pqhi, *pkhi, *pvhi, *pohi;
    cudaGetSymbolAddress(&pxhi, g_xhi);
    cudaGetSymbolAddress(&pwhi, g_wThi);
    cudaGetSymbolAddress(&pqhi, g_qhi);
    cudaGetSymbolAddress(&pkhi, g_khi);
    cudaGetSymbolAddress(&pvhi, g_vhi);
    cudaGetSymbolAddress(&pohi, g_ohi);

    __half* xhi = (__half*)pxhi;
    __half* whi = (__half*)pwhi;

    static bool attr_set = false;
    if (!attr_set) {
        cudaFuncSetAttribute(gemm_qkv,  cudaFuncAttributeMaxDynamicSharedMemorySize, G_SMEM);
        cudaFuncSetAttribute(gemm_out,  cudaFuncAttributeMaxDynamicSharedMemorySize, G_SMEM);
        cudaFuncSetAttribute(flash_mma, cudaFuncAttributeMaxDynamicSharedMemorySize, F_SMEM);
        attr_set = true;
    }

    // launch 1: all prep (x convert + 4 weight transposes)
    dim3 pgrid(32, 32, 5), pblk(32, 8);
    prep_all<<<pgrid, pblk>>>(x, Wq, Wk, Wv, Wo, xhi, whi);

    // launch 2: fused QKV projections
    dim3 qgrid(GN / 64, GM / 128, 3);   // (16, 32, 3)
    gemm_qkv<<<qgrid, 256, G_SMEM>>>(xhi, whi, bq, bk, bv,
                                     (__half*)pqhi, (__half*)pkhi, (__half*)pvhi);

    // launch 3: attention
    dim3 fgrid(SS / 128, HH, BB);       // (16, 16, 2)
    flash_mma<<<fgrid, 256, F_SMEM>>>(cause, effect, strength);

    // launch 4: output projection
    dim3 ogrid(GN / 64, GM / 128);      // (16, 32)
    gemm_out<<<ogrid, 256, G_SMEM>>>((__half*)pohi,
                                     whi + 3*(size_t)DD*DD, bo, out);
}

// round 16
// speedup vs baseline: 1.0546x; 1.0546x over previous
#include <cuda_runtime.h>
#include <cuda_fp16.h>
#include <cstdint>

#define BB 2
#define SS 2048
#define DD 1024
#define HH 16
#define HD 64
#define GM (BB*SS)   // 4096
#define GN DD
#define GK DD

// ---------------------------------------------------------------------------
// Device-global scratch (fp16)
// ---------------------------------------------------------------------------
__device__ __half g_xhi[GM*DD];
__device__ __half g_wThi[4*DD*DD];      // W^T [N,K]
__device__ __half g_qhi[GM*DD];          // [B,H,S,HD], pre-scaled log2e/8
__device__ __half g_khi[GM*DD];
__device__ __half g_vhi[GM*DD];
__device__ __half g_ohi[GM*DD];          // [B*S, D] attn out

// ---------------------------------------------------------------------------
// Helpers
// ---------------------------------------------------------------------------
__device__ __forceinline__ uint32_t smem_u32(const void* p) {
    uint32_t a;
    asm("{ .reg .u64 t; cvta.to.shared.u64 t, %1; cvt.u32.u64 %0, t; }"
        : "=r"(a) : "l"(p));
    return a;
}

__device__ __forceinline__ uint32_t swz(uint32_t row, uint32_t cc) {
    return row * 128u + ((cc ^ (row & 7u)) << 4);
}

__device__ __forceinline__ void cp_async16(uint32_t s, const void* g) {
    asm volatile("cp.async.cg.shared.global [%0], [%1], 16;" :: "r"(s), "l"(g));
}
__device__ __forceinline__ void cp_async4(uint32_t s, const void* g) {
    asm volatile("cp.async.ca.shared.global [%0], [%1], 4;" :: "r"(s), "l"(g));
}
#define CP_COMMIT()  asm volatile("cp.async.commit_group;")
#define CP_WAIT1()   asm volatile("cp.async.wait_group 1;")
#define CP_WAIT0()   asm volatile("cp.async.wait_group 0;")

__device__ __forceinline__ void ldsm_x4(uint32_t* r, uint32_t a) {
    asm volatile("ldmatrix.sync.aligned.m8n8.x4.shared.b16 {%0,%1,%2,%3}, [%4];"
        : "=r"(r[0]), "=r"(r[1]), "=r"(r[2]), "=r"(r[3]) : "r"(a));
}
__device__ __forceinline__ void ldsm_x4_t(uint32_t* r, uint32_t a) {
    asm volatile("ldmatrix.sync.aligned.m8n8.x4.trans.shared.b16 {%0,%1,%2,%3}, [%4];"
        : "=r"(r[0]), "=r"(r[1]), "=r"(r[2]), "=r"(r[3]) : "r"(a));
}

__device__ __forceinline__ void mma_f32(float* c, const uint32_t* a, const uint32_t* b) {
    asm volatile(
        "mma.sync.aligned.m16n8k16.row.col.f32.f16.f16.f32 "
        "{%0,%1,%2,%3}, {%4,%5,%6,%7}, {%8,%9}, {%0,%1,%2,%3};"
        : "+f"(c[0]), "+f"(c[1]), "+f"(c[2]), "+f"(c[3])
        : "r"(a[0]), "r"(a[1]), "r"(a[2]), "r"(a[3]), "r"(b[0]), "r"(b[1]));
}

__device__ __forceinline__ uint32_t hpack(float a, float b) {
    __half2 h = __floats2half2_rn(a, b);
    return *reinterpret_cast<uint32_t*>(&h);
}

// single MUFU.EX2
__device__ __forceinline__ float ex2(float x) {
    float r;
    asm("ex2.approx.f32 %0, %1;" : "=f"(r) : "f"(x));
    return r;
}

// ---------------------------------------------------------------------------
// Merged prep: z=0..3 transpose W[z] -> W^T fp16; z=4 convert x -> fp16.
// ---------------------------------------------------------------------------
__global__ __launch_bounds__(256)
void prep_all(const float* __restrict__ x,
              const float* __restrict__ W0, const float* __restrict__ W1,
              const float* __restrict__ W2, const float* __restrict__ W3,
              __half* __restrict__ xhi, __half* __restrict__ hiT)
{
    const int z = blockIdx.z;
    const int tid = threadIdx.y * 32 + threadIdx.x;
    if (z == 4) {
        const int bid = blockIdx.y * 32 + blockIdx.x;
        const float4* src = (const float4*)x + (size_t)bid * 1024;
        uint32_t* dst = (uint32_t*)xhi + (size_t)bid * 2048;
#pragma unroll
        for (int it = 0; it < 4; ++it) {
            const int i = it * 256 + tid;
            float4 v = src[i];
            dst[2*i]   = hpack(v.x, v.y);
            dst[2*i+1] = hpack(v.z, v.w);
        }
        return;
    }
    __shared__ float t[32][33];
    const float* W = (z == 0) ? W0 : (z == 1) ? W1 : (z == 2) ? W2 : W3;
    __half* ho = hiT + (size_t)z * DD * DD;
    const int tx = threadIdx.x, ty = threadIdx.y;
    const int n0 = blockIdx.x * 32, k0 = blockIdx.y * 32;
#pragma unroll
    for (int r = ty; r < 32; r += 8)
        t[r][tx] = W[(size_t)(k0 + r) * GN + n0 + tx];
    __syncthreads();
#pragma unroll
    for (int r = ty; r < 32; r += 8)
        ho[(size_t)(n0 + r) * GK + k0 + tx] = __float2half_rn(t[tx][r]);
}

// ---------------------------------------------------------------------------
// GEMM core, 1-pass fp16, 128x128 CTA tile, 2-stage pipeline.
// 8 warps as 4M x 2N (warp tile 32x64), cached fragments.
// ---------------------------------------------------------------------------
#define G_AH 0
#define G_BH 16384
#define G_STAGE 32768
#define G_SMEM (2*G_STAGE)   // 64KB -> 2 CTAs/SM

struct GemmCtx {
    uint32_t sb;
    int row, cc0;            // same loader pattern for A and B (128 rows each)
    const __half *gAh, *gBh;
};

__device__ __forceinline__ void gemm_issue(const GemmCtx& g, int stage) {
    const uint32_t buf = g.sb + (stage & 1) * G_STAGE;
    const int ko = stage * 64;
#pragma unroll
    for (int i = 0; i < 4; ++i) {
        cp_async16(buf + G_AH + swz(g.row, g.cc0 + i), g.gAh + ko + i * 8);
        cp_async16(buf + G_BH + swz(g.row, g.cc0 + i), g.gBh + ko + i * 8);
    }
    CP_COMMIT();
}

__device__ __forceinline__ void gemm_mainloop(const GemmCtx& g, int lane,
                                              int wm, int wn, float c[2][8][4]) {
    gemm_issue(g, 0);
    for (int s = 0; s < 16; ++s) {
        if (s + 1 < 16) { gemm_issue(g, s + 1); CP_WAIT1(); } else { CP_WAIT0(); }
        __syncthreads();
        const uint32_t base = g.sb + (s & 1) * G_STAGE;
#pragma unroll
        for (int kt = 0; kt < 4; ++kt) {
            uint32_t a0[4], a1[4];
            const uint32_t ar = wm * 32 + (lane & 15);
            const uint32_t ac = kt * 2 + (lane >> 4);
            ldsm_x4(a0, base + G_AH + swz(ar, ac));
            ldsm_x4(a1, base + G_AH + swz(ar + 16, ac));
#pragma unroll
            for (int np = 0; np < 4; ++np) {
                uint32_t bh[4];
                const uint32_t br  = wn * 64 + (2 * np + (lane >> 4)) * 8 + (lane & 7);
                const uint32_t bcc = kt * 2 + ((lane >> 3) & 1);
                ldsm_x4(bh, base + G_BH + swz(br, bcc));
                mma_f32(c[0][2*np],   a0, bh); mma_f32(c[0][2*np+1], a0, bh + 2);
                mma_f32(c[1][2*np],   a1, bh); mma_f32(c[1][2*np+1], a1, bh + 2);
            }
        }
        __syncthreads();
    }
}

// Fused QKV projection (1-pass): grid (8, 32, 3)
// Q scale folds softmax 1/sqrt(HD) AND log2(e).
__global__ __launch_bounds__(256, 2)
void gemm_qkv(const __half* __restrict__ Ahi, const __half* __restrict__ Whi,
              const float* __restrict__ bq, const float* __restrict__ bk,
              const float* __restrict__ bv,
              __half* __restrict__ qhi, __half* __restrict__ khi,
              __half* __restrict__ vhi)
{
    extern __shared__ char smraw[];
    const int tid = threadIdx.x, lane = tid & 31, warp = tid >> 5;
    const int wm = warp >> 1, wn = warp & 1;
    const int m0 = blockIdx.y * 128, n0 = blockIdx.x * 128;
    const int z = blockIdx.z;

    const float* bias = (z == 0) ? bq : (z == 1) ? bk : bv;
    __half* Chi = (z == 0) ? qhi : (z == 1) ? khi : vhi;
    const float scale = (z == 0) ? (0.125f * 1.4426950408889634f) : 1.0f;
    const __half* Bhi = Whi + (size_t)z * DD * DD;

    GemmCtx g;
    g.sb = smem_u32(smraw);
    g.row = tid >> 1;  g.cc0 = (tid & 1) * 4;
    g.gAh = Ahi + (size_t)(m0 + g.row) * GK + g.cc0 * 8;
    g.gBh = Bhi + (size_t)(n0 + g.row) * GK + g.cc0 * 8;

    float c[2][8][4];
#pragma unroll
    for (int a = 0; a < 2; ++a)
#pragma unroll
        for (int b = 0; b < 8; ++b)
#pragma unroll
            for (int e = 0; e < 4; ++e) c[a][b][e] = 0.f;

    gemm_mainloop(g, lane, wm, wn, c);

#pragma unroll
    for (int mt = 0; mt < 2; ++mt) {
#pragma unroll
        for (int nt = 0; nt < 8; ++nt) {
            const int col = n0 + wn * 64 + nt * 8 + (lane & 3) * 2;
            const float2 bs = *(const float2*)(bias + col);
#pragma unroll
            for (int hf = 0; hf < 2; ++hf) {
                const int row = m0 + wm * 32 + mt * 16 + (lane >> 2) + hf * 8;
                const float v0 = (c[mt][nt][hf*2]     + bs.x) * scale;
                const float v1 = (c[mt][nt][hf*2 + 1] + bs.y) * scale;
                const int bb = row >> 11, sq = row & 2047;
                const int hh = col >> 6,  hd = col & 63;
                const size_t off = (((size_t)(bb * HH + hh)) * SS + sq) * HD + hd;
                *(uint32_t*)(Chi + off) = hpack(v0, v1);
            }
        }
    }
}

// Output projection (1-pass): grid (8, 32), fp32 C + bias
__global__ __launch_bounds__(256, 2)
void gemm_out(const __half* __restrict__ Ahi, const __half* __restrict__ Bhi,
              const float* __restrict__ bias, float* __restrict__ C)
{
    extern __shared__ char smraw[];
    const int tid = threadIdx.x, lane = tid & 31, warp = tid >> 5;
    const int wm = warp >> 1, wn = warp & 1;
    const int m0 = blockIdx.y * 128, n0 = blockIdx.x * 128;

    GemmCtx g;
    g.sb = smem_u32(smraw);
    g.row = tid >> 1;  g.cc0 = (tid & 1) * 4;
    g.gAh = Ahi + (size_t)(m0 + g.row) * GK + g.cc0 * 8;
    g.gBh = Bhi + (size_t)(n0 + g.row) * GK + g.cc0 * 8;

    float c[2][8][4];
#pragma unroll
    for (int a = 0; a < 2; ++a)
#pragma unroll
        for (int b = 0; b < 8; ++b)
#pragma unroll
            for (int e = 0; e < 4; ++e) c[a][b][e] = 0.f;

    gemm_mainloop(g, lane, wm, wn, c);

#pragma unroll
    for (int mt = 0; mt < 2; ++mt) {
#pragma unroll
        for (int nt = 0; nt < 8; ++nt) {
            const int col = n0 + wn * 64 + nt * 8 + (lane & 3) * 2;
            const float2 bs = *(const float2*)(bias + col);
#pragma unroll
            for (int hf = 0; hf < 2; ++hf) {
                const int row = m0 + wm * 32 + mt * 16 + (lane >> 2) + hf * 8;
                const float v0 = c[mt][nt][hf*2]     + bs.x;
                const float v1 = c[mt][nt][hf*2 + 1] + bs.y;
                *(float2*)(C + (size_t)row * GN + col) = make_float2(v0, v1);
            }
        }
    }
}

// ---------------------------------------------------------------------------
// Flash attention, fixed-shift softmax, 2-stage K/V pipeline (R14 config).
// ---------------------------------------------------------------------------
#define F_QHI 0
#define F_ST0 16384
#define F_STSZ 16384
#define F_KHI 0
#define F_VHI 8192
#define F_EMI (F_ST0 + 2*F_STSZ)
#define F_CMI (F_EMI + 512)
#define F_SMEM (F_CMI + 512)

__global__ __launch_bounds__(256, 2)
void flash_mma(const int* __restrict__ cause, const int* __restrict__ effect,
               const float* __restrict__ strength)
{
    extern __shared__ char smraw[];
    const uint32_t sb = smem_u32(smraw);
    const int tid = threadIdx.x, lane = tid & 31, warp = tid >> 5;
    const int b = blockIdx.z, h = blockIdx.y, q0 = blockIdx.x * 128;
    const float fm1 = 1.0f - 0.5f * strength[0];

    const size_t headoff = ((size_t)(b * HH + h)) * SS;

    {   // prologue: Q-hi + cause mask (joins stage-0 commit group)
        const __half* qsrc = g_qhi + (headoff + q0) * HD;
        const int r = tid >> 1, c0 = (tid & 1) * 4;
#pragma unroll
        for (int i = 0; i < 4; ++i)
            cp_async16(sb + F_QHI + swz(r, c0 + i),
                       qsrc + (size_t)r * HD + (c0 + i) * 8);
        if (tid < 128) cp_async4(sb + F_CMI + tid * 4, cause + b * SS + q0 + tid);
    }

    auto issue = [&](int s) {
        const uint32_t st = sb + F_ST0 + (s & 1) * F_STSZ;
        const int kt0 = s * 64;
        const __half* srcs[2] = { g_khi + (headoff + kt0) * HD,
                                  g_vhi + (headoff + kt0) * HD };
        const int r = tid >> 2, cc0 = (tid & 3) * 2;
#pragma unroll
        for (int t = 0; t < 2; ++t)
#pragma unroll
            for (int i = 0; i < 2; ++i)
                cp_async16(st + t * 8192 + swz(r, cc0 + i),
                           srcs[t] + (size_t)r * HD + (cc0 + i) * 8);
        if (tid < 64) cp_async4(sb + F_EMI + (s & 1) * 256 + tid * 4,
                                effect + b * SS + kt0 + tid);
        CP_COMMIT();
    };

    issue(0);

    float o[8][4];
#pragma unroll
    for (int i = 0; i < 8; ++i)
#pragma unroll
        for (int e = 0; e < 4; ++e) o[i][e] = 0.f;
    float lrow0 = 0.f, lrow1 = 0.f;
    uint32_t qh[4][4];
    int cm0 = 0, cm1 = 0;

    for (int s = 0; s < 32; ++s) {
        if (s + 1 < 32) { issue(s + 1); CP_WAIT1(); } else { CP_WAIT0(); }
        __syncthreads();

        if (s == 0) {
            const uint32_t ar = warp * 16 + (lane & 15);
#pragma unroll
            for (int kt = 0; kt < 4; ++kt)
                ldsm_x4(qh[kt], sb + F_QHI + swz(ar, kt * 2 + (lane >> 4)));
            const int* cmi = (const int*)(smraw + F_CMI);
            cm0 = cmi[warp * 16 + (lane >> 2)];
            cm1 = cmi[warp * 16 + (lane >> 2) + 8];
        }

        const uint32_t st = sb + F_ST0 + (s & 1) * F_STSZ;

        // ---- S = Qh Kh  (log2 domain)
        float sc[8][4];
#pragma unroll
        for (int i = 0; i < 8; ++i)
            sc[i][0] = sc[i][1] = sc[i][2] = sc[i][3] = 0.f;
#pragma unroll
        for (int kt = 0; kt < 4; ++kt) {
#pragma unroll
            for (int np = 0; np < 4; ++np) {
                uint32_t kh[4];
                const uint32_t br  = (2 * np + (lane >> 4)) * 8 + (lane & 7);
                const uint32_t bcc = kt * 2 + ((lane >> 3) & 1);
                ldsm_x4(kh, st + F_KHI + swz(br, bcc));
                mma_f32(sc[2*np], qh[kt], kh); mma_f32(sc[2*np+1], qh[kt], kh + 2);
            }
        }

        // ---- mask + fixed-shift softmax: P = ex2(S*mask)
        const int* emi = (const int*)(smraw + F_EMI + (s & 1) * 256);
        uint32_t pha[8], phb[8];
#pragma unroll
        for (int nt = 0; nt < 8; ++nt) {
            const int col = nt * 8 + (lane & 3) * 2;
            const int e0 = emi[col], e1 = emi[col + 1];
            const float p0 = ex2(sc[nt][0] * ((cm0 && e0) ? fm1 : 1.0f));
            const float p1 = ex2(sc[nt][1] * ((cm0 && e1) ? fm1 : 1.0f));
            const float p2 = ex2(sc[nt][2] * ((cm1 && e0) ? fm1 : 1.0f));
            const float p3 = ex2(sc[nt][3] * ((cm1 && e1) ? fm1 : 1.0f));
            lrow0 += p0 + p1;
            lrow1 += p2 + p3;
            pha[nt] = hpack(p0, p1);
            phb[nt] = hpack(p2, p3);
        }

        // ---- O += Ph Vh
#pragma unroll
        for (int kt = 0; kt < 4; ++kt) {
            uint32_t ph[4] = { pha[2*kt], phb[2*kt], pha[2*kt+1], phb[2*kt+1] };
#pragma unroll
            for (int np = 0; np < 4; ++np) {
                uint32_t vh[4];
                const uint32_t vr  = kt * 16 + (((lane >> 3) & 1) << 3) + (lane & 7);
                const uint32_t vcc = 2 * np + (lane >> 4);
                ldsm_x4_t(vh, st + F_VHI + swz(vr, vcc));
                mma_f32(o[2*np], ph, vh); mma_f32(o[2*np+1], ph, vh + 2);
            }
        }
        __syncthreads();
    }

    // ---- epilogue: single cross-lane row-sum reduce, normalize, store
    lrow0 += __shfl_xor_sync(0xffffffffu, lrow0, 1);
    lrow0 += __shfl_xor_sync(0xffffffffu, lrow0, 2);
    lrow1 += __shfl_xor_sync(0xffffffffu, lrow1, 1);
    lrow1 += __shfl_xor_sync(0xffffffffu, lrow1, 2);
    const float inv0 = 1.0f / lrow0, inv1 = 1.0f / lrow1;
    const int row0 = b * SS + q0 + warp * 16 + (lane >> 2);
#pragma unroll
    for (int nt = 0; nt < 8; ++nt) {
        const int col = h * 64 + nt * 8 + (lane & 3) * 2;
        const float v0 = o[nt][0] * inv0, v1 = o[nt][1] * inv0;
        const float v2 = o[nt][2] * inv1, v3 = o[nt][3] * inv1;
        *(uint32_t*)(g_ohi + (size_t)row0 * DD + col)       = hpack(v0, v1);
        *(uint32_t*)(g_ohi + (size_t)(row0 + 8) * DD + col) = hpack(v2, v3);
    }
}

// ---------------------------------------------------------------------------
extern "C" void kernel_launch(void* const* d_in, const int* in_sizes, int n_in,
                              void* d_out, int out_size)
{
    const float* x        = (const float*)d_in[0];
    const int*   cause    = (const int*)d_in[1];
    const int*   effect   = (const int*)d_in[2];
    const float* strength = (const float*)d_in[3];
    const float* Wq = (const float*)d_in[4];
    const float* bq = (const float*)d_in[5];
    const float* Wk = (const float*)d_in[6];
    const float* bk = (const float*)d_in[7];
    const float* Wv = (const float*)d_in[8];
    const float* bv = (const float*)d_in[9];
    const float* Wo = (const float*)d_in[10];
    const float* bo = (const float*)d_in[11];
    float* out = (float*)d_out;

    void *pxhi, *pwhi, *pqhi, *pkhi, *pvhi, *pohi;
    cudaGetSymbolAddress(&pxhi, g_xhi);
    cudaGetSymbolAddress(&pwhi, g_wThi);
    cudaGetSymbolAddress(&pqhi, g_qhi);
    cudaGetSymbolAddress(&pkhi, g_khi);
    cudaGetSymbolAddress(&pvhi, g_vhi);
    cudaGetSymbolAddress(&pohi, g_ohi);

    __half* xhi = (__half*)pxhi;
    __half* whi = (__half*)pwhi;

    static bool attr_set = false;
    if (!attr_set) {
        cudaFuncSetAttribute(gemm_qkv,  cudaFuncAttributeMaxDynamicSharedMemorySize, G_SMEM);
        cudaFuncSetAttribute(gemm_out,  cudaFuncAttributeMaxDynamicSharedMemorySize, G_SMEM);
        cudaFuncSetAttribute(flash_mma, cudaFuncAttributeMaxDynamicSharedMemorySize, F_SMEM);
        attr_set = true;
    }

    // launch 1: all prep (x convert + 4 weight transposes)
    dim3 pgrid(32, 32, 5), pblk(32, 8);
    prep_all<<<pgrid, pblk>>>(x, Wq, Wk, Wv, Wo, xhi, whi);

    // launch 2: fused QKV projections
    dim3 qgrid(GN / 128, GM / 128, 3);  // (8, 32, 3) = 768 CTAs
    gemm_qkv<<<qgrid, 256, G_SMEM>>>(xhi, whi, bq, bk, bv,
                                     (__half*)pqhi, (__half*)pkhi, (__half*)pvhi);

    // launch 3: attention
    dim3 fgrid(SS / 128, HH, BB);       // (16, 16, 2)
    flash_mma<<<fgrid, 256, F_SMEM>>>(cause, effect, strength);

    // launch 4: output projection
    dim3 ogrid(GN / 128, GM / 128);     // (8, 32) = 256 CTAs, single wave
    gemm_out<<<ogrid, 256, G_SMEM>>>((__half*)pohi,
                                     whi + 3*(size_t)DD*DD, bo, out);
}